// round 1
// baseline (speedup 1.0000x reference)
#include <cuda_runtime.h>
#include <math.h>

#define HIDDEN 512
#define E_DIM  1024
#define S_DIM  128
#define NB     32
#define NSEQ   1024
#define BTOK   (NB * NSEQ)          // 32768 tokens
#define UVC    (2 * E_DIM + S_DIM)  // 2176
#define HALF   64

// ---------------- scratch (device globals; no runtime allocation) ----------
__device__ float g_scale[BTOK];                       // per-token norm scale
__device__ float g_uv[(size_t)BTOK * UVC];            // silu(x@Wuv+b)  285 MB
__device__ float g_q[BTOK * S_DIM];                   // 16 MB
__device__ float g_k[BTOK * S_DIM];                   // 16 MB
__device__ float g_scores[(size_t)NB * NSEQ * NSEQ];  // 134 MB
__device__ float g_attn[(size_t)BTOK * E_DIM];        // 134 MB
__device__ float g_sinT[NSEQ * HALF];
__device__ float g_cosT[NSEQ * HALF];

// ---------------- trig table -----------------------------------------------
// inv_freq = 10000^(j/64)  (positive exponent per reference!). Arguments get
// huge (~1e7); compute freq in double, round to f32, do the pos*freq product
// in f32 (to match the reference's f32 sinusoid), then take sin/cos in double
// of that exact f32 argument.
__global__ void trig_kernel() {
    int t = blockIdx.x * blockDim.x + threadIdx.x;
    if (t >= NSEQ * HALF) return;
    int pos = t >> 6;
    int j   = t & 63;
    double freq_d = pow(10000.0, (double)j / 64.0);
    float  freq_f = (float)freq_d;
    float  arg    = __fmul_rn((float)pos, freq_f);
    double a      = (double)arg;
    g_sinT[t] = (float)sin(a);
    g_cosT[t] = (float)cos(a);
}

// ---------------- per-token scale ------------------------------------------
__global__ void scale_kernel(const float* __restrict__ x,
                             const float* __restrict__ g) {
    int m = blockIdx.x;
    const float* xr = x + (size_t)m * HIDDEN;
    float ss = 0.f;
    for (int i = threadIdx.x; i < HIDDEN; i += 256) {
        float v = xr[i];
        ss = fmaf(v, v, ss);
    }
    #pragma unroll
    for (int o = 16; o; o >>= 1) ss += __shfl_xor_sync(0xffffffffu, ss, o);
    __shared__ float red[8];
    if ((threadIdx.x & 31) == 0) red[threadIdx.x >> 5] = ss;
    __syncthreads();
    if (threadIdx.x == 0) {
        float t = 0.f;
        #pragma unroll
        for (int i = 0; i < 8; i++) t += red[i];
        float norm = sqrtf(t) * 0.04419417382415922f;  // * 512^-0.5
        g_scale[m] = g[0] / fmaxf(norm, 1e-5f);
    }
}

// ---------------- GEMM 1: uv = silu((x*s) @ Wuv + buv) ---------------------
// M=32768, N=2176, K=512. 128x128 tile, BK=8, 256 thr, 8x8 microtile.
__global__ __launch_bounds__(256) void gemm_uv(const float* __restrict__ x,
                                               const float* __restrict__ W,
                                               const float* __restrict__ buv) {
    const int bm = blockIdx.y * 128;
    const int bn = blockIdx.x * 128;
    __shared__ float As[8][128];
    __shared__ float Bs[8][128];
    float acc[8][8] = {};
    const int tid = threadIdx.x;
    const int tx = tid & 15, ty = tid >> 4;
    const int arow = tid >> 1, acol = (tid & 1) * 4;
    const int brow = tid >> 5, bcol = (tid & 31) * 4;
    const float* Ap = x + (size_t)(bm + arow) * HIDDEN + acol;
    const float* Bp = W + (size_t)brow * UVC + bn + bcol;
    const float s = g_scale[bm + arow];
    for (int k0 = 0; k0 < HIDDEN; k0 += 8) {
        float4 av = *(const float4*)(Ap + k0);
        float4 bv = *(const float4*)(Bp + (size_t)k0 * UVC);
        As[acol + 0][arow] = av.x * s;
        As[acol + 1][arow] = av.y * s;
        As[acol + 2][arow] = av.z * s;
        As[acol + 3][arow] = av.w * s;
        *(float4*)&Bs[brow][bcol] = bv;
        __syncthreads();
        #pragma unroll
        for (int k = 0; k < 8; ++k) {
            float ar[8], br[8];
            *(float4*)&ar[0] = *(const float4*)&As[k][ty * 8];
            *(float4*)&ar[4] = *(const float4*)&As[k][ty * 8 + 4];
            *(float4*)&br[0] = *(const float4*)&Bs[k][tx * 8];
            *(float4*)&br[4] = *(const float4*)&Bs[k][tx * 8 + 4];
            #pragma unroll
            for (int i = 0; i < 8; i++)
                #pragma unroll
                for (int j = 0; j < 8; j++)
                    acc[i][j] = fmaf(ar[i], br[j], acc[i][j]);
        }
        __syncthreads();
    }
    #pragma unroll
    for (int i = 0; i < 8; i++) {
        int row = bm + ty * 8 + i;
        float* crow = g_uv + (size_t)row * UVC;
        #pragma unroll
        for (int j = 0; j < 8; j++) {
            int col = bn + tx * 8 + j;
            float vz = acc[i][j] + buv[col];
            crow[col] = vz / (1.0f + expf(-vz));  // silu
        }
    }
}

// ---------------- RoPE + gamma/beta → q, k ---------------------------------
__global__ void rope_kernel(const float* __restrict__ gamma,
                            const float* __restrict__ beta) {
    int m = blockIdx.x;
    int j = threadIdx.x;  // 0..63
    int pos = m & (NSEQ - 1);
    const float* base = g_uv + (size_t)m * UVC + 2 * E_DIM;
    float b1 = base[j];
    float b2 = base[j + HALF];
    float c  = g_cosT[pos * HALF + j];
    float sn = g_sinT[pos * HALF + j];
    // q (gamma/beta row 0)
    float q1 = b1 * gamma[j] + beta[j];
    float q2 = b2 * gamma[j + HALF] + beta[j + HALF];
    g_q[m * S_DIM + j]        = q1 * c - q2 * sn;
    g_q[m * S_DIM + j + HALF] = q2 * c + q1 * sn;
    // k (gamma/beta row 1)
    float k1 = b1 * gamma[S_DIM + j] + beta[S_DIM + j];
    float k2 = b2 * gamma[S_DIM + j + HALF] + beta[S_DIM + j + HALF];
    g_k[m * S_DIM + j]        = k1 * c - k2 * sn;
    g_k[m * S_DIM + j + HALF] = k2 * c + k1 * sn;
}

// ---------------- GEMM 2 (NT, batched): scores = relu(qk/sqrt(S))^2 --------
// per batch: M=1024, N=1024, K=128
__global__ __launch_bounds__(256) void gemm_scores() {
    const int b  = blockIdx.z;
    const int bm = blockIdx.y * 128;
    const int bn = blockIdx.x * 128;
    const float* q  = g_q + (size_t)b * NSEQ * S_DIM;
    const float* kk = g_k + (size_t)b * NSEQ * S_DIM;
    __shared__ float As[8][128];
    __shared__ float Bs[8][128];
    float acc[8][8] = {};
    const int tid = threadIdx.x;
    const int tx = tid & 15, ty = tid >> 4;
    const int arow = tid >> 1, acol = (tid & 1) * 4;
    const float* Ap = q  + (size_t)(bm + arow) * S_DIM + acol;
    const float* Bp = kk + (size_t)(bn + arow) * S_DIM + acol;
    for (int k0 = 0; k0 < S_DIM; k0 += 8) {
        float4 av = *(const float4*)(Ap + k0);
        float4 bv = *(const float4*)(Bp + k0);
        As[acol + 0][arow] = av.x;
        As[acol + 1][arow] = av.y;
        As[acol + 2][arow] = av.z;
        As[acol + 3][arow] = av.w;
        Bs[acol + 0][arow] = bv.x;
        Bs[acol + 1][arow] = bv.y;
        Bs[acol + 2][arow] = bv.z;
        Bs[acol + 3][arow] = bv.w;
        __syncthreads();
        #pragma unroll
        for (int k = 0; k < 8; ++k) {
            float ar[8], br[8];
            *(float4*)&ar[0] = *(const float4*)&As[k][ty * 8];
            *(float4*)&ar[4] = *(const float4*)&As[k][ty * 8 + 4];
            *(float4*)&br[0] = *(const float4*)&Bs[k][tx * 8];
            *(float4*)&br[4] = *(const float4*)&Bs[k][tx * 8 + 4];
            #pragma unroll
            for (int i = 0; i < 8; i++)
                #pragma unroll
                for (int j = 0; j < 8; j++)
                    acc[i][j] = fmaf(ar[i], br[j], acc[i][j]);
        }
        __syncthreads();
    }
    float* srow0 = g_scores + (size_t)b * NSEQ * NSEQ;
    #pragma unroll
    for (int i = 0; i < 8; i++) {
        int row = bm + ty * 8 + i;
        #pragma unroll
        for (int j = 0; j < 8; j++) {
            int col = bn + tx * 8 + j;
            float w = acc[i][j] / 11.313708498984761f;  // / sqrt(128)
            w = fmaxf(w, 0.f);
            srow0[(size_t)row * NSEQ + col] = w * w;
        }
    }
}

// ---------------- GEMM 3 (NN, batched): attn = u * (scores @ v) ------------
// per batch: M=1024, N=1024(E), K=1024
__global__ __launch_bounds__(256) void gemm_attn() {
    const int b  = blockIdx.z;
    const int bm = blockIdx.y * 128;
    const int bn = blockIdx.x * 128;
    const float* A = g_scores + (size_t)b * NSEQ * NSEQ;
    const float* V = g_uv + (size_t)b * NSEQ * UVC + E_DIM;  // v at col 1024
    __shared__ float As[8][128];
    __shared__ float Bs[8][128];
    float acc[8][8] = {};
    const int tid = threadIdx.x;
    const int tx = tid & 15, ty = tid >> 4;
    const int arow = tid >> 1, acol = (tid & 1) * 4;
    const int brow = tid >> 5, bcol = (tid & 31) * 4;
    const float* Ap = A + (size_t)(bm + arow) * NSEQ + acol;
    const float* Bp = V + (size_t)brow * UVC + bn + bcol;
    for (int k0 = 0; k0 < NSEQ; k0 += 8) {
        float4 av = *(const float4*)(Ap + k0);
        float4 bv = *(const float4*)(Bp + (size_t)k0 * UVC);
        As[acol + 0][arow] = av.x;
        As[acol + 1][arow] = av.y;
        As[acol + 2][arow] = av.z;
        As[acol + 3][arow] = av.w;
        *(float4*)&Bs[brow][bcol] = bv;
        __syncthreads();
        #pragma unroll
        for (int k = 0; k < 8; ++k) {
            float ar[8], br[8];
            *(float4*)&ar[0] = *(const float4*)&As[k][ty * 8];
            *(float4*)&ar[4] = *(const float4*)&As[k][ty * 8 + 4];
            *(float4*)&br[0] = *(const float4*)&Bs[k][tx * 8];
            *(float4*)&br[4] = *(const float4*)&Bs[k][tx * 8 + 4];
            #pragma unroll
            for (int i = 0; i < 8; i++)
                #pragma unroll
                for (int j = 0; j < 8; j++)
                    acc[i][j] = fmaf(ar[i], br[j], acc[i][j]);
        }
        __syncthreads();
    }
    #pragma unroll
    for (int i = 0; i < 8; i++) {
        int row = bm + ty * 8 + i;             // seq position within batch
        size_t tok = (size_t)b * NSEQ + row;
        const float* urow = g_uv + tok * UVC;  // u at col 0
        float* orow = g_attn + tok * E_DIM;
        #pragma unroll
        for (int j = 0; j < 8; j++) {
            int col = bn + tx * 8 + j;
            orow[col] = acc[i][j] * urow[col];
        }
    }
}

// ---------------- GEMM 4: out = attn @ Wo + bo + x -------------------------
// M=32768, N=512, K=1024
__global__ __launch_bounds__(256) void gemm_out(const float* __restrict__ Wo,
                                                const float* __restrict__ bo,
                                                const float* __restrict__ x,
                                                float* __restrict__ out) {
    const int bm = blockIdx.y * 128;
    const int bn = blockIdx.x * 128;
    __shared__ float As[8][128];
    __shared__ float Bs[8][128];
    float acc[8][8] = {};
    const int tid = threadIdx.x;
    const int tx = tid & 15, ty = tid >> 4;
    const int arow = tid >> 1, acol = (tid & 1) * 4;
    const int brow = tid >> 5, bcol = (tid & 31) * 4;
    const float* Ap = g_attn + (size_t)(bm + arow) * E_DIM + acol;
    const float* Bp = Wo + (size_t)brow * HIDDEN + bn + bcol;
    for (int k0 = 0; k0 < E_DIM; k0 += 8) {
        float4 av = *(const float4*)(Ap + k0);
        float4 bv = *(const float4*)(Bp + (size_t)k0 * HIDDEN);
        As[acol + 0][arow] = av.x;
        As[acol + 1][arow] = av.y;
        As[acol + 2][arow] = av.z;
        As[acol + 3][arow] = av.w;
        *(float4*)&Bs[brow][bcol] = bv;
        __syncthreads();
        #pragma unroll
        for (int k = 0; k < 8; ++k) {
            float ar[8], br[8];
            *(float4*)&ar[0] = *(const float4*)&As[k][ty * 8];
            *(float4*)&ar[4] = *(const float4*)&As[k][ty * 8 + 4];
            *(float4*)&br[0] = *(const float4*)&Bs[k][tx * 8];
            *(float4*)&br[4] = *(const float4*)&Bs[k][tx * 8 + 4];
            #pragma unroll
            for (int i = 0; i < 8; i++)
                #pragma unroll
                for (int j = 0; j < 8; j++)
                    acc[i][j] = fmaf(ar[i], br[j], acc[i][j]);
        }
        __syncthreads();
    }
    #pragma unroll
    for (int i = 0; i < 8; i++) {
        int row = bm + ty * 8 + i;
        const float* xrow = x + (size_t)row * HIDDEN;
        float* orow = out + (size_t)row * HIDDEN;
        #pragma unroll
        for (int j = 0; j < 8; j++) {
            int col = bn + tx * 8 + j;
            orow[col] = acc[i][j] + bo[col] + xrow[col];
        }
    }
}

// ---------------- launcher -------------------------------------------------
extern "C" void kernel_launch(void* const* d_in, const int* in_sizes, int n_in,
                              void* d_out, int out_size) {
    const float* x     = (const float*)d_in[0];
    const float* Wuv   = (const float*)d_in[1];
    const float* buv   = (const float*)d_in[2];
    const float* gamma = (const float*)d_in[3];
    const float* beta  = (const float*)d_in[4];
    const float* Wo    = (const float*)d_in[5];
    const float* bo    = (const float*)d_in[6];
    const float* g     = (const float*)d_in[7];
    float* out = (float*)d_out;

    trig_kernel<<<(NSEQ * HALF + 255) / 256, 256>>>();
    scale_kernel<<<BTOK, 256>>>(x, g);
    gemm_uv<<<dim3(UVC / 128, BTOK / 128), 256>>>(x, Wuv, buv);
    rope_kernel<<<BTOK, HALF>>>(gamma, beta);
    gemm_scores<<<dim3(NSEQ / 128, NSEQ / 128, NB), 256>>>();
    gemm_attn<<<dim3(E_DIM / 128, NSEQ / 128, NB), 256>>>();
    gemm_out<<<dim3(HIDDEN / 128, BTOK / 128), 256>>>(Wo, bo, x, out);
}

// round 7
// speedup vs baseline: 1.1087x; 1.1087x over previous
#include <cuda_runtime.h>
#include <cuda_bf16.h>
#include <cstdint>
#include <math.h>

#define HIDDEN 512
#define E_DIM  1024
#define S_DIM  128
#define NB     32
#define NSEQ   1024
#define BTOK   (NB * NSEQ)
#define UVC    (2 * E_DIM + S_DIM)   // 2176
#define HALF   64

#define TM 128
#define TN 128

// ---------------- scratch (device globals) ---------------------------------
__device__ float g_scale[BTOK];
__device__ float g_uv[(size_t)BTOK * UVC];
__device__ float g_q[BTOK * S_DIM];
__device__ float g_k[BTOK * S_DIM];
__device__ float g_scores[(size_t)NB * NSEQ * NSEQ];
__device__ float g_attn[(size_t)BTOK * E_DIM];
__device__ float g_vT[(size_t)NB * E_DIM * NSEQ];
__device__ float g_WuvT[(size_t)UVC * HIDDEN];
__device__ float g_WoT[(size_t)HIDDEN * E_DIM];
__device__ float g_sinT[NSEQ * HALF];
__device__ float g_cosT[NSEQ * HALF];

// ---------------- mma.sync bf16 --------------------------------------------
__device__ __forceinline__ void mma_bf16(float* d, const uint32_t* a, const uint32_t* b) {
    asm volatile(
        "mma.sync.aligned.m16n8k16.row.col.f32.bf16.bf16.f32 "
        "{%0,%1,%2,%3}, {%4,%5,%6,%7}, {%8,%9}, {%0,%1,%2,%3};"
        : "+f"(d[0]), "+f"(d[1]), "+f"(d[2]), "+f"(d[3])
        : "r"(a[0]), "r"(a[1]), "r"(a[2]), "r"(a[3]), "r"(b[0]), "r"(b[1]));
}

// fp32 pair -> packed bf16 hi + packed bf16 lo
__device__ __forceinline__ void split2(float2 v, uint32_t& hi, uint32_t& lo) {
    __nv_bfloat16 h0 = __float2bfloat16(v.x);
    __nv_bfloat16 h1 = __float2bfloat16(v.y);
    __nv_bfloat16 l0 = __float2bfloat16(v.x - __bfloat162float(h0));
    __nv_bfloat16 l1 = __float2bfloat16(v.y - __bfloat162float(h1));
    hi = ((uint32_t)__bfloat16_as_ushort(h1) << 16) | __bfloat16_as_ushort(h0);
    lo = ((uint32_t)__bfloat16_as_ushort(l1) << 16) | __bfloat16_as_ushort(l0);
}

// ---------------- unified GEMM core (direct-GMEM fragments) ----------------
// C[128,128] = A[128,K] * B[128,K]^T, both K-major. fp32 via bf16 hi/lo 3-MMA.
template <class Epi>
__device__ __forceinline__ void gemm_core(const float* __restrict__ A, int lda,
                                          const float* __restrict__ B, int ldb,
                                          int K, const float* __restrict__ rowscale,
                                          Epi epi) {
    const int tid  = threadIdx.x;
    const int lane = tid & 31;
    const int wid  = tid >> 5;
    const int wm   = wid >> 2;          // 0..1
    const int wn   = wid & 3;           // 0..3
    const int g    = lane >> 2;         // 0..7
    const int tg   = lane & 3;          // 0..3
    const int r0   = wm * 64;
    const int n0   = wn * 32;

    float acc[4][4][4];
    #pragma unroll
    for (int i = 0; i < 4; i++)
        #pragma unroll
        for (int j = 0; j < 4; j++)
            #pragma unroll
            for (int t = 0; t < 4; t++) acc[i][j][t] = 0.f;

    for (int k0 = 0; k0 < K; k0 += 16) {
        // ---- B fragments for the 4 n-tiles ----
        uint32_t bh[4][2], bl[4][2];
        #pragma unroll
        for (int nt = 0; nt < 4; ++nt) {
            const float* Bp = B + (size_t)(n0 + nt * 8 + g) * ldb + k0 + 2 * tg;
            float2 v0 = *(const float2*)Bp;         // k = 2tg, 2tg+1
            float2 v1 = *(const float2*)(Bp + 8);   // k = 2tg+8, +9
            split2(v0, bh[nt][0], bl[nt][0]);
            split2(v1, bh[nt][1], bl[nt][1]);
        }
        // ---- A fragments per m-tile, then MMAs ----
        #pragma unroll
        for (int mt = 0; mt < 4; ++mt) {
            const int ra = r0 + mt * 16 + g;
            const float* Ap  = A + (size_t)ra * lda + k0 + 2 * tg;
            const float* Ap8 = Ap + 8 * lda;
            float2 u0 = *(const float2*)Ap;          // a0: row g,   k 2tg
            float2 u1 = *(const float2*)Ap8;         // a1: row g+8, k 2tg
            float2 u2 = *(const float2*)(Ap + 8);    // a2: row g,   k 2tg+8
            float2 u3 = *(const float2*)(Ap8 + 8);   // a3: row g+8, k 2tg+8
            if (rowscale) {
                float s0 = __ldg(rowscale + ra);
                float s1 = __ldg(rowscale + ra + 8);
                u0.x *= s0; u0.y *= s0; u2.x *= s0; u2.y *= s0;
                u1.x *= s1; u1.y *= s1; u3.x *= s1; u3.y *= s1;
            }
            uint32_t ah[4], al[4];
            split2(u0, ah[0], al[0]);
            split2(u1, ah[1], al[1]);
            split2(u2, ah[2], al[2]);
            split2(u3, ah[3], al[3]);
            #pragma unroll
            for (int nt = 0; nt < 4; ++nt) {
                mma_bf16(acc[mt][nt], ah, bh[nt]);
                mma_bf16(acc[mt][nt], ah, bl[nt]);
                mma_bf16(acc[mt][nt], al, bh[nt]);
            }
        }
    }

    // ---- epilogue from registers ----
    #pragma unroll
    for (int mt = 0; mt < 4; ++mt) {
        int row0 = r0 + mt * 16 + g;
        #pragma unroll
        for (int nt = 0; nt < 4; ++nt) {
            int col = n0 + nt * 8 + tg * 2;
            epi(row0,     col, acc[mt][nt][0], acc[mt][nt][1]);
            epi(row0 + 8, col, acc[mt][nt][2], acc[mt][nt][3]);
        }
    }
}

// ---------------- GEMM kernels ---------------------------------------------
struct EpiUV {
    const float* buv; int bm, bn;
    __device__ __forceinline__ void operator()(int r, int c, float a, float b) const {
        float va = a + buv[bn + c];
        float vb = b + buv[bn + c + 1];
        float* p = g_uv + (size_t)(bm + r) * UVC + bn + c;
        p[0] = va / (1.0f + __expf(-va));
        p[1] = vb / (1.0f + __expf(-vb));
    }
};
__global__ __launch_bounds__(256) void k_gemm_uv(const float* __restrict__ x,
                                                 const float* __restrict__ buv) {
    const int bm = blockIdx.y * TM, bn = blockIdx.x * TN;
    gemm_core(x + (size_t)bm * HIDDEN, HIDDEN,
              g_WuvT + (size_t)bn * HIDDEN, HIDDEN, HIDDEN,
              g_scale + bm, EpiUV{buv, bm, bn});
}

struct EpiScores {
    float* dst; int bm, bn;
    __device__ __forceinline__ void operator()(int r, int c, float a, float b) const {
        float wa = fmaxf(a * 0.08838834764831845f, 0.f);
        float wb = fmaxf(b * 0.08838834764831845f, 0.f);
        float* p = dst + (size_t)(bm + r) * NSEQ + bn + c;
        p[0] = wa * wa;
        p[1] = wb * wb;
    }
};
__global__ __launch_bounds__(256) void k_gemm_scores() {
    const int b = blockIdx.z;
    const int bm = blockIdx.y * TM, bn = blockIdx.x * TN;
    gemm_core(g_q + (size_t)b * NSEQ * S_DIM + (size_t)bm * S_DIM, S_DIM,
              g_k + (size_t)b * NSEQ * S_DIM + (size_t)bn * S_DIM, S_DIM, S_DIM,
              nullptr, EpiScores{g_scores + (size_t)b * NSEQ * NSEQ, bm, bn});
}

struct EpiAttn {
    int b, bm, bn;
    __device__ __forceinline__ void operator()(int r, int c, float a, float bvv) const {
        size_t tok = (size_t)b * NSEQ + bm + r;
        const float* u = g_uv + tok * UVC + bn + c;
        float* p = g_attn + tok * E_DIM + bn + c;
        p[0] = a * u[0];
        p[1] = bvv * u[1];
    }
};
__global__ __launch_bounds__(256) void k_gemm_attn() {
    const int b = blockIdx.z;
    const int bm = blockIdx.y * TM, bn = blockIdx.x * TN;
    gemm_core(g_scores + (size_t)b * NSEQ * NSEQ + (size_t)bm * NSEQ, NSEQ,
              g_vT + (size_t)b * E_DIM * NSEQ + (size_t)bn * NSEQ, NSEQ, NSEQ,
              nullptr, EpiAttn{b, bm, bn});
}

struct EpiOut {
    const float* x; const float* bo; float* out; int bm, bn;
    __device__ __forceinline__ void operator()(int r, int c, float a, float b) const {
        size_t row = bm + r;
        int col = bn + c;
        out[row * HIDDEN + col]     = a + bo[col]     + x[row * HIDDEN + col];
        out[row * HIDDEN + col + 1] = b + bo[col + 1] + x[row * HIDDEN + col + 1];
    }
};
__global__ __launch_bounds__(256) void k_gemm_out(const float* __restrict__ x,
                                                  const float* __restrict__ bo,
                                                  float* __restrict__ out) {
    const int bm = blockIdx.y * TM, bn = blockIdx.x * TN;
    gemm_core(g_attn + (size_t)bm * E_DIM, E_DIM,
              g_WoT + (size_t)bn * E_DIM, E_DIM, E_DIM,
              nullptr, EpiOut{x, bo, out, bm, bn});
}

// ---------------- transposes (dst = device global, referenced DEVICE-side) --
// FIX R7: never pass __device__ globals as host-side kernel arguments.
__device__ __forceinline__ void transpose_body(const float* __restrict__ src,
                                               float* __restrict__ dst,
                                               int R, int C) {
    __shared__ float t[32][33];
    int c0 = blockIdx.x * 32, r0 = blockIdx.y * 32;
    int tx = threadIdx.x, ty = threadIdx.y;
    #pragma unroll
    for (int j = 0; j < 32; j += 8)
        t[ty + j][tx] = src[(size_t)(r0 + ty + j) * C + c0 + tx];
    __syncthreads();
    #pragma unroll
    for (int j = 0; j < 32; j += 8)
        dst[(size_t)(c0 + ty + j) * R + r0 + tx] = t[tx][ty + j];
}

__global__ void k_transpose_wuv(const float* __restrict__ Wuv) {
    transpose_body(Wuv, g_WuvT, HIDDEN, UVC);    // [512,2176] -> [2176,512]
}
__global__ void k_transpose_wo(const float* __restrict__ Wo) {
    transpose_body(Wo, g_WoT, E_DIM, HIDDEN);    // [1024,512] -> [512,1024]
}

__global__ void k_transpose_v() {
    __shared__ float t[32][33];
    int b = blockIdx.z;
    const float* src = g_uv + (size_t)b * NSEQ * UVC + E_DIM;
    float* dst = g_vT + (size_t)b * E_DIM * NSEQ;
    int c0 = blockIdx.x * 32, r0 = blockIdx.y * 32;
    int tx = threadIdx.x, ty = threadIdx.y;
    #pragma unroll
    for (int j = 0; j < 32; j += 8)
        t[ty + j][tx] = src[(size_t)(r0 + ty + j) * UVC + c0 + tx];
    __syncthreads();
    #pragma unroll
    for (int j = 0; j < 32; j += 8)
        dst[(size_t)(c0 + ty + j) * NSEQ + r0 + tx] = t[tx][ty + j];
}

// ---------------- small kernels --------------------------------------------
__global__ void trig_kernel() {
    int t = blockIdx.x * blockDim.x + threadIdx.x;
    if (t >= NSEQ * HALF) return;
    int pos = t >> 6;
    int j = t & 63;
    double freq_d = pow(10000.0, (double)j / 64.0);
    float freq_f = (float)freq_d;
    float arg = __fmul_rn((float)pos, freq_f);
    double a = (double)arg;
    g_sinT[t] = (float)sin(a);
    g_cosT[t] = (float)cos(a);
}

__global__ void scale_kernel(const float* __restrict__ x, const float* __restrict__ g) {
    int m = blockIdx.x;
    const float* xr = x + (size_t)m * HIDDEN;
    float ss = 0.f;
    for (int i = threadIdx.x; i < HIDDEN; i += 256) {
        float v = xr[i];
        ss = fmaf(v, v, ss);
    }
    #pragma unroll
    for (int o = 16; o; o >>= 1) ss += __shfl_xor_sync(0xffffffffu, ss, o);
    __shared__ float red[8];
    if ((threadIdx.x & 31) == 0) red[threadIdx.x >> 5] = ss;
    __syncthreads();
    if (threadIdx.x == 0) {
        float t = 0.f;
        #pragma unroll
        for (int i = 0; i < 8; i++) t += red[i];
        float norm = sqrtf(t) * 0.04419417382415922f;
        g_scale[m] = g[0] / fmaxf(norm, 1e-5f);
    }
}

__global__ void rope_kernel(const float* __restrict__ gamma, const float* __restrict__ beta) {
    int m = blockIdx.x;
    int j = threadIdx.x;
    int pos = m & (NSEQ - 1);
    const float* base = g_uv + (size_t)m * UVC + 2 * E_DIM;
    float b1 = base[j];
    float b2 = base[j + HALF];
    float c = g_cosT[pos * HALF + j];
    float sn = g_sinT[pos * HALF + j];
    float q1 = b1 * gamma[j] + beta[j];
    float q2 = b2 * gamma[j + HALF] + beta[j + HALF];
    g_q[m * S_DIM + j] = q1 * c - q2 * sn;
    g_q[m * S_DIM + j + HALF] = q2 * c + q1 * sn;
    float k1 = b1 * gamma[S_DIM + j] + beta[S_DIM + j];
    float k2 = b2 * gamma[S_DIM + j + HALF] + beta[S_DIM + j + HALF];
    g_k[m * S_DIM + j] = k1 * c - k2 * sn;
    g_k[m * S_DIM + j + HALF] = k2 * c + k1 * sn;
}

// ---------------- launcher -------------------------------------------------
extern "C" void kernel_launch(void* const* d_in, const int* in_sizes, int n_in,
                              void* d_out, int out_size) {
    const float* x     = (const float*)d_in[0];
    const float* Wuv   = (const float*)d_in[1];
    const float* buv   = (const float*)d_in[2];
    const float* gamma = (const float*)d_in[3];
    const float* beta  = (const float*)d_in[4];
    const float* Wo    = (const float*)d_in[5];
    const float* bo    = (const float*)d_in[6];
    const float* g     = (const float*)d_in[7];
    float* out = (float*)d_out;

    trig_kernel<<<(NSEQ * HALF + 255) / 256, 256>>>();
    scale_kernel<<<BTOK, 256>>>(x, g);
    k_transpose_wuv<<<dim3(UVC / 32, HIDDEN / 32), dim3(32, 8)>>>(Wuv);
    k_transpose_wo<<<dim3(HIDDEN / 32, E_DIM / 32), dim3(32, 8)>>>(Wo);
    k_gemm_uv<<<dim3(UVC / TN, BTOK / TM), 256>>>(x, buv);
    k_transpose_v<<<dim3(E_DIM / 32, NSEQ / 32, NB), dim3(32, 8)>>>();
    rope_kernel<<<BTOK, HALF>>>(gamma, beta);
    k_gemm_scores<<<dim3(NSEQ / TN, NSEQ / TM, NB), 256>>>();
    k_gemm_attn<<<dim3(E_DIM / TN, NSEQ / TM, NB), 256>>>();
    k_gemm_out<<<dim3(HIDDEN / TN, BTOK / TM), 256>>>(x, bo, out);
}

// round 8
// speedup vs baseline: 1.8132x; 1.6355x over previous
#include <cuda_runtime.h>
#include <cuda_bf16.h>
#include <cstdint>
#include <math.h>

#define HIDDEN 512
#define E_DIM  1024
#define S_DIM  128
#define NB     32
#define NSEQ   1024
#define BTOK   (NB * NSEQ)
#define UVC    (2 * E_DIM + S_DIM)   // 2176
#define HALF   64

#define TM 128
#define TN 128
#define TKC 32                        // fp32 K per chunk
#define STRB 80                       // padded row stride in bytes (40 bf16)
#define AHI 0
#define ALO 10240
#define BHI 20480
#define BLO 30720
#define BUF_BYTES 40960               // single static buffer

// ---------------- scratch (device globals) ---------------------------------
__device__ float g_scale[BTOK];
__device__ float g_uv[(size_t)BTOK * UVC];
__device__ float g_q[BTOK * S_DIM];
__device__ float g_k[BTOK * S_DIM];
__device__ float g_scores[(size_t)NB * NSEQ * NSEQ];
__device__ float g_attn[(size_t)BTOK * E_DIM];
__device__ float g_vT[(size_t)NB * E_DIM * NSEQ];
__device__ float g_WuvT[(size_t)UVC * HIDDEN];
__device__ float g_WoT[(size_t)HIDDEN * E_DIM];
__device__ float g_sinT[NSEQ * HALF];
__device__ float g_cosT[NSEQ * HALF];

// ---------------- PTX helpers ----------------------------------------------
__device__ __forceinline__ uint32_t smem_u32(const void* p) {
    uint32_t a;
    asm("{ .reg .u64 t; cvta.to.shared.u64 t, %1; cvt.u32.u64 %0, t; }"
        : "=r"(a) : "l"(p));
    return a;
}
__device__ __forceinline__ void ldm_x4(uint32_t* r, uint32_t addr) {
    asm volatile("ldmatrix.sync.aligned.m8n8.x4.shared.b16 {%0,%1,%2,%3}, [%4];"
        : "=r"(r[0]), "=r"(r[1]), "=r"(r[2]), "=r"(r[3]) : "r"(addr));
}
__device__ __forceinline__ void mma_bf16(float* d, const uint32_t* a, const uint32_t* b) {
    asm volatile(
        "mma.sync.aligned.m16n8k16.row.col.f32.bf16.bf16.f32 "
        "{%0,%1,%2,%3}, {%4,%5,%6,%7}, {%8,%9}, {%0,%1,%2,%3};"
        : "+f"(d[0]), "+f"(d[1]), "+f"(d[2]), "+f"(d[3])
        : "r"(a[0]), "r"(a[1]), "r"(a[2]), "r"(a[3]), "r"(b[0]), "r"(b[1]));
}

// fp32x4 -> packed bf16 hi pair + lo pair
__device__ __forceinline__ void split4(float4 v, uint2& hi, uint2& lo) {
    __nv_bfloat16 h0 = __float2bfloat16(v.x);
    __nv_bfloat16 h1 = __float2bfloat16(v.y);
    __nv_bfloat16 h2 = __float2bfloat16(v.z);
    __nv_bfloat16 h3 = __float2bfloat16(v.w);
    __nv_bfloat16 l0 = __float2bfloat16(v.x - __bfloat162float(h0));
    __nv_bfloat16 l1 = __float2bfloat16(v.y - __bfloat162float(h1));
    __nv_bfloat16 l2 = __float2bfloat16(v.z - __bfloat162float(h2));
    __nv_bfloat16 l3 = __float2bfloat16(v.w - __bfloat162float(h3));
    hi.x = ((uint32_t)__bfloat16_as_ushort(h1) << 16) | __bfloat16_as_ushort(h0);
    hi.y = ((uint32_t)__bfloat16_as_ushort(h3) << 16) | __bfloat16_as_ushort(h2);
    lo.x = ((uint32_t)__bfloat16_as_ushort(l1) << 16) | __bfloat16_as_ushort(l0);
    lo.y = ((uint32_t)__bfloat16_as_ushort(l3) << 16) | __bfloat16_as_ushort(l2);
}

// ---------------- unified GEMM core ----------------------------------------
// C[128,128] = A[128,K] * B[128,K]^T, both K-major. fp32 via bf16 hi/lo 3-MMA.
// Single smem buffer + register prefetch: LDG for chunk c+1 issues before the
// MMAs of chunk c, hiding GMEM latency without double-buffered smem.
template <class Epi>
__device__ __forceinline__ void gemm_core(const float* __restrict__ A, int lda,
                                          const float* __restrict__ B, int ldb,
                                          int K, const float* __restrict__ rowscale,
                                          Epi epi) {
    __shared__ char smem[BUF_BYTES];
    const int tid  = threadIdx.x;
    const int lane = tid & 31;
    const int wid  = tid >> 5;
    const int wm   = wid >> 2;             // 0..1
    const int wn   = wid & 3;              // 0..3
    const int g    = lane >> 2;            // 0..7
    const int tg   = lane & 3;             // 0..3
    const int lrow = lane & 15;            // ldmatrix row select
    const int lhalf = (lane >> 4) * 16;    // ldmatrix k-half byte offset
    const uint32_t sbase = smem_u32(smem);

    // per-thread staging coordinates: thread covers row = tid/8 (+32/iter),
    // 4-float group c4 = tid%8
    const int srow = tid >> 3;
    const int c4   = tid & 7;

    float acc[4][4][4];
    #pragma unroll
    for (int i = 0; i < 4; i++)
        #pragma unroll
        for (int j = 0; j < 4; j++)
            #pragma unroll
            for (int t = 0; t < 4; t++) acc[i][j][t] = 0.f;

    const int NC = K / TKC;

    // rowscale values for this thread's 4 rows (constant across chunks)
    float rs[4];
    #pragma unroll
    for (int i = 0; i < 4; i++)
        rs[i] = rowscale ? __ldg(rowscale + srow + i * 32) : 1.0f;

    // prefetch chunk 0
    float4 ra[4], rb[4];
    #pragma unroll
    for (int i = 0; i < 4; i++) {
        int row = srow + i * 32;
        ra[i] = *(const float4*)(A + (size_t)row * lda + c4 * 4);
        rb[i] = *(const float4*)(B + (size_t)row * ldb + c4 * 4);
    }

    for (int c = 0; c < NC; ++c) {
        __syncthreads();     // previous chunk's ldmatrix reads complete
        #pragma unroll
        for (int i = 0; i < 4; i++) {
            int row = srow + i * 32;
            float4 v = ra[i];
            v.x *= rs[i]; v.y *= rs[i]; v.z *= rs[i]; v.w *= rs[i];
            uint2 hi, lo;
            split4(v, hi, lo);
            *(uint2*)(smem + AHI + row * STRB + c4 * 8) = hi;
            *(uint2*)(smem + ALO + row * STRB + c4 * 8) = lo;
            split4(rb[i], hi, lo);
            *(uint2*)(smem + BHI + row * STRB + c4 * 8) = hi;
            *(uint2*)(smem + BLO + row * STRB + c4 * 8) = lo;
        }
        __syncthreads();     // tiles visible

        // issue next chunk's LDGs now; latency hides behind the MMAs below
        if (c + 1 < NC) {
            const float* An = A + (c + 1) * TKC;
            const float* Bn = B + (c + 1) * TKC;
            #pragma unroll
            for (int i = 0; i < 4; i++) {
                int row = srow + i * 32;
                ra[i] = *(const float4*)(An + (size_t)row * lda + c4 * 4);
                rb[i] = *(const float4*)(Bn + (size_t)row * ldb + c4 * 4);
            }
        }

        #pragma unroll
        for (int ks = 0; ks < 2; ++ks) {
            const int kb = ks * 32 + lhalf;      // byte offset along k
            uint32_t bh[4][2], bl[4][2];
            #pragma unroll
            for (int h = 0; h < 2; ++h) {
                uint32_t r4[4];
                ldm_x4(r4, sbase + BHI + (wn * 32 + h * 16 + lrow) * STRB + kb);
                bh[2*h][0] = r4[0]; bh[2*h+1][0] = r4[1];
                bh[2*h][1] = r4[2]; bh[2*h+1][1] = r4[3];
                ldm_x4(r4, sbase + BLO + (wn * 32 + h * 16 + lrow) * STRB + kb);
                bl[2*h][0] = r4[0]; bl[2*h+1][0] = r4[1];
                bl[2*h][1] = r4[2]; bl[2*h+1][1] = r4[3];
            }
            #pragma unroll
            for (int mt = 0; mt < 4; ++mt) {
                uint32_t ah[4], al[4];
                ldm_x4(ah, sbase + AHI + (wm * 64 + mt * 16 + lrow) * STRB + kb);
                ldm_x4(al, sbase + ALO + (wm * 64 + mt * 16 + lrow) * STRB + kb);
                #pragma unroll
                for (int nt = 0; nt < 4; ++nt) {
                    mma_bf16(acc[mt][nt], ah, bh[nt]);
                    mma_bf16(acc[mt][nt], ah, bl[nt]);
                    mma_bf16(acc[mt][nt], al, bh[nt]);
                }
            }
        }
    }

    // ---- epilogue from registers ----
    #pragma unroll
    for (int mt = 0; mt < 4; ++mt) {
        int row0 = wm * 64 + mt * 16 + g;
        #pragma unroll
        for (int nt = 0; nt < 4; ++nt) {
            int col = wn * 32 + nt * 8 + tg * 2;
            epi(row0,     col, acc[mt][nt][0], acc[mt][nt][1]);
            epi(row0 + 8, col, acc[mt][nt][2], acc[mt][nt][3]);
        }
    }
}

// ---------------- GEMM kernels ---------------------------------------------
struct EpiUV {
    const float* buv; int bm, bn;
    __device__ __forceinline__ void operator()(int r, int c, float a, float b) const {
        float va = a + buv[bn + c];
        float vb = b + buv[bn + c + 1];
        float* p = g_uv + (size_t)(bm + r) * UVC + bn + c;
        p[0] = va / (1.0f + __expf(-va));
        p[1] = vb / (1.0f + __expf(-vb));
    }
};
__global__ __launch_bounds__(256) void k_gemm_uv(const float* __restrict__ x,
                                                 const float* __restrict__ buv) {
    const int bm = blockIdx.y * TM, bn = blockIdx.x * TN;
    gemm_core(x + (size_t)bm * HIDDEN, HIDDEN,
              g_WuvT + (size_t)bn * HIDDEN, HIDDEN, HIDDEN,
              g_scale + bm, EpiUV{buv, bm, bn});
}

struct EpiScores {
    float* dst; int bm, bn;
    __device__ __forceinline__ void operator()(int r, int c, float a, float b) const {
        float wa = fmaxf(a * 0.08838834764831845f, 0.f);
        float wb = fmaxf(b * 0.08838834764831845f, 0.f);
        float* p = dst + (size_t)(bm + r) * NSEQ + bn + c;
        p[0] = wa * wa;
        p[1] = wb * wb;
    }
};
__global__ __launch_bounds__(256) void k_gemm_scores() {
    const int b = blockIdx.z;
    const int bm = blockIdx.y * TM, bn = blockIdx.x * TN;
    gemm_core(g_q + (size_t)b * NSEQ * S_DIM + (size_t)bm * S_DIM, S_DIM,
              g_k + (size_t)b * NSEQ * S_DIM + (size_t)bn * S_DIM, S_DIM, S_DIM,
              nullptr, EpiScores{g_scores + (size_t)b * NSEQ * NSEQ, bm, bn});
}

struct EpiAttn {
    int b, bm, bn;
    __device__ __forceinline__ void operator()(int r, int c, float a, float bvv) const {
        size_t tok = (size_t)b * NSEQ + bm + r;
        const float* u = g_uv + tok * UVC + bn + c;
        float* p = g_attn + tok * E_DIM + bn + c;
        p[0] = a * u[0];
        p[1] = bvv * u[1];
    }
};
__global__ __launch_bounds__(256) void k_gemm_attn() {
    const int b = blockIdx.z;
    const int bm = blockIdx.y * TM, bn = blockIdx.x * TN;
    gemm_core(g_scores + (size_t)b * NSEQ * NSEQ + (size_t)bm * NSEQ, NSEQ,
              g_vT + (size_t)b * E_DIM * NSEQ + (size_t)bn * NSEQ, NSEQ, NSEQ,
              nullptr, EpiAttn{b, bm, bn});
}

struct EpiOut {
    const float* x; const float* bo; float* out; int bm, bn;
    __device__ __forceinline__ void operator()(int r, int c, float a, float b) const {
        size_t row = bm + r;
        int col = bn + c;
        out[row * HIDDEN + col]     = a + bo[col]     + x[row * HIDDEN + col];
        out[row * HIDDEN + col + 1] = b + bo[col + 1] + x[row * HIDDEN + col + 1];
    }
};
__global__ __launch_bounds__(256) void k_gemm_out(const float* __restrict__ x,
                                                  const float* __restrict__ bo,
                                                  float* __restrict__ out) {
    const int bm = blockIdx.y * TM, bn = blockIdx.x * TN;
    gemm_core(g_attn + (size_t)bm * E_DIM, E_DIM,
              g_WoT + (size_t)bn * E_DIM, E_DIM, E_DIM,
              nullptr, EpiOut{x, bo, out, bm, bn});
}

// ---------------- transposes (dst referenced device-side only) -------------
__device__ __forceinline__ void transpose_body(const float* __restrict__ src,
                                               float* __restrict__ dst,
                                               int R, int C) {
    __shared__ float t[32][33];
    int c0 = blockIdx.x * 32, r0 = blockIdx.y * 32;
    int tx = threadIdx.x, ty = threadIdx.y;
    #pragma unroll
    for (int j = 0; j < 32; j += 8)
        t[ty + j][tx] = src[(size_t)(r0 + ty + j) * C + c0 + tx];
    __syncthreads();
    #pragma unroll
    for (int j = 0; j < 32; j += 8)
        dst[(size_t)(c0 + ty + j) * R + r0 + tx] = t[tx][ty + j];
}

__global__ void k_transpose_wuv(const float* __restrict__ Wuv) {
    transpose_body(Wuv, g_WuvT, HIDDEN, UVC);
}
__global__ void k_transpose_wo(const float* __restrict__ Wo) {
    transpose_body(Wo, g_WoT, E_DIM, HIDDEN);
}

__global__ void k_transpose_v() {
    __shared__ float t[32][33];
    int b = blockIdx.z;
    const float* src = g_uv + (size_t)b * NSEQ * UVC + E_DIM;
    float* dst = g_vT + (size_t)b * E_DIM * NSEQ;
    int c0 = blockIdx.x * 32, r0 = blockIdx.y * 32;
    int tx = threadIdx.x, ty = threadIdx.y;
    #pragma unroll
    for (int j = 0; j < 32; j += 8)
        t[ty + j][tx] = src[(size_t)(r0 + ty + j) * UVC + c0 + tx];
    __syncthreads();
    #pragma unroll
    for (int j = 0; j < 32; j += 8)
        dst[(size_t)(c0 + ty + j) * NSEQ + r0 + tx] = t[tx][ty + j];
}

// ---------------- small kernels --------------------------------------------
__global__ void trig_kernel() {
    int t = blockIdx.x * blockDim.x + threadIdx.x;
    if (t >= NSEQ * HALF) return;
    int pos = t >> 6;
    int j = t & 63;
    double freq_d = pow(10000.0, (double)j / 64.0);
    float freq_f = (float)freq_d;
    float arg = __fmul_rn((float)pos, freq_f);
    double a = (double)arg;
    g_sinT[t] = (float)sin(a);
    g_cosT[t] = (float)cos(a);
}

__global__ void scale_kernel(const float* __restrict__ x, const float* __restrict__ g) {
    int m = blockIdx.x;
    const float* xr = x + (size_t)m * HIDDEN;
    float ss = 0.f;
    for (int i = threadIdx.x; i < HIDDEN; i += 256) {
        float v = xr[i];
        ss = fmaf(v, v, ss);
    }
    #pragma unroll
    for (int o = 16; o; o >>= 1) ss += __shfl_xor_sync(0xffffffffu, ss, o);
    __shared__ float red[8];
    if ((threadIdx.x & 31) == 0) red[threadIdx.x >> 5] = ss;
    __syncthreads();
    if (threadIdx.x == 0) {
        float t = 0.f;
        #pragma unroll
        for (int i = 0; i < 8; i++) t += red[i];
        float norm = sqrtf(t) * 0.04419417382415922f;
        g_scale[m] = g[0] / fmaxf(norm, 1e-5f);
    }
}

__global__ void rope_kernel(const float* __restrict__ gamma, const float* __restrict__ beta) {
    int m = blockIdx.x;
    int j = threadIdx.x;
    int pos = m & (NSEQ - 1);
    const float* base = g_uv + (size_t)m * UVC + 2 * E_DIM;
    float b1 = base[j];
    float b2 = base[j + HALF];
    float c = g_cosT[pos * HALF + j];
    float sn = g_sinT[pos * HALF + j];
    float q1 = b1 * gamma[j] + beta[j];
    float q2 = b2 * gamma[j + HALF] + beta[j + HALF];
    g_q[m * S_DIM + j] = q1 * c - q2 * sn;
    g_q[m * S_DIM + j + HALF] = q2 * c + q1 * sn;
    float k1 = b1 * gamma[S_DIM + j] + beta[S_DIM + j];
    float k2 = b2 * gamma[S_DIM + j + HALF] + beta[S_DIM + j + HALF];
    g_k[m * S_DIM + j] = k1 * c - k2 * sn;
    g_k[m * S_DIM + j + HALF] = k2 * c + k1 * sn;
}

// ---------------- launcher -------------------------------------------------
extern "C" void kernel_launch(void* const* d_in, const int* in_sizes, int n_in,
                              void* d_out, int out_size) {
    const float* x     = (const float*)d_in[0];
    const float* Wuv   = (const float*)d_in[1];
    const float* buv   = (const float*)d_in[2];
    const float* gamma = (const float*)d_in[3];
    const float* beta  = (const float*)d_in[4];
    const float* Wo    = (const float*)d_in[5];
    const float* bo    = (const float*)d_in[6];
    const float* g     = (const float*)d_in[7];
    float* out = (float*)d_out;

    trig_kernel<<<(NSEQ * HALF + 255) / 256, 256>>>();
    scale_kernel<<<BTOK, 256>>>(x, g);
    k_transpose_wuv<<<dim3(UVC / 32, HIDDEN / 32), dim3(32, 8)>>>(Wuv);
    k_transpose_wo<<<dim3(HIDDEN / 32, E_DIM / 32), dim3(32, 8)>>>(Wo);
    k_gemm_uv<<<dim3(UVC / TN, BTOK / TM), 256>>>(x, buv);
    k_transpose_v<<<dim3(E_DIM / 32, NSEQ / 32, NB), dim3(32, 8)>>>();
    rope_kernel<<<BTOK, HALF>>>(gamma, beta);
    k_gemm_scores<<<dim3(NSEQ / TN, NSEQ / TM, NB), 256>>>();
    k_gemm_attn<<<dim3(E_DIM / TN, NSEQ / TM, NB), 256>>>();
    k_gemm_out<<<dim3(HIDDEN / TN, BTOK / TM), 256>>>(x, bo, out);
}